// round 2
// baseline (speedup 1.0000x reference)
#include <cuda_runtime.h>

#define N_NODES 16384
#define DEG 16
#define H 128
#define G4 512           // 4*H
#define NPC 64           // nodes per CTA
#define KT 32            // k-tile
#define NT 256           // threads per CTA

// Pre-transposed weights: g_WT[s][k][col] = W[col*H + k], s=0 -> W_ih, s=1 -> W_hh
__device__ float g_WT[2][H][G4];

__global__ void transpose_w_kernel(const float* __restrict__ Wih,
                                   const float* __restrict__ Whh) {
    int idx = blockIdx.x * blockDim.x + threadIdx.x;
    if (idx < G4 * H) {
        int col = idx / H, k = idx % H;
        g_WT[0][k][col] = Wih[idx];
        g_WT[1][k][col] = Whh[idx];
    }
}

__device__ __forceinline__ float sigmoidf_fast(float v) {
    return 1.0f / (1.0f + __expf(-v));
}
__device__ __forceinline__ float lo_f32(unsigned long long v) {
    return __int_as_float((int)(unsigned int)v);
}
__device__ __forceinline__ float hi_f32(unsigned long long v) {
    return __int_as_float((int)(v >> 32));
}

__global__ __launch_bounds__(NT, 1)
void lstm_agg_kernel(const float* __restrict__ x,
                     const float* __restrict__ b_ih,
                     const float* __restrict__ b_hh,
                     float* __restrict__ out) {
    extern __shared__ float sm[];
    float* sh_x = sm;                  // NPC*H
    float* sh_h = sh_x + NPC * H;      // NPC*H
    float* sh_c = sh_h + NPC * H;      // NPC*H
    float* wt   = sh_c + NPC * H;      // KT*G4
    float* bias = wt + KT * G4;        // G4

    const int tid  = threadIdx.x;
    const int tx   = tid & 31;         // column group 0..31
    const int ty   = tid >> 5;         // row group 0..7
    const int row0 = ty * 8;
    const int colq = tx * 4;           // base col within a gate (0..127, step 4)
    const int n0   = blockIdx.x * NPC;

    for (int i = tid; i < G4; i += NT) bias[i] = b_ih[i] + b_hh[i];
    for (int i = tid; i < NPC * H; i += NT) { sh_h[i] = 0.0f; sh_c[i] = 0.0f; }
    __syncthreads();

    #pragma unroll 1
    for (int t = 0; t < DEG; ++t) {
        // ---- load x_t tile: 64 rows x 128 (prev-step reads of sh_x fenced by sync C) ----
        #pragma unroll
        for (int j = tid; j < NPC * H / 4; j += NT) {
            int m  = j >> 5;           // j / 32
            int k4 = j & 31;           // j % 32
            ((float4*)sh_x)[j] =
                *(const float4*)(x + ((size_t)(n0 + m) * DEG + t) * H + k4 * 4);
        }

        // ---- init accumulators with bias (f32x2 pairs) ----
        // acc2[r][g*2+p] holds gate cols (g*128 + colq + 2p, +2p+1) for row row0+r
        unsigned long long acc2[8][8];
        #pragma unroll
        for (int g = 0; g < 4; ++g) {
            ulonglong2 bb = *(const ulonglong2*)(bias + g * 128 + colq);
            #pragma unroll
            for (int r = 0; r < 8; ++r) {
                acc2[r][g * 2]     = bb.x;
                acc2[r][g * 2 + 1] = bb.y;
            }
        }

        // ---- GEMM: acc += src(64x128) @ WT(128x512), src = x_t then h ----
        #pragma unroll 1
        for (int s = 0; s < 2; ++s) {
            const float* src = (s == 0) ? sh_x : sh_h;
            #pragma unroll 1
            for (int kc = 0; kc < H; kc += KT) {
                __syncthreads();   // wt free; (first tile) sh_x ready / prev-step h-writes done
                // stage weight tile KT x G4 (contiguous in g_WT) -> smem
                const float4* wsrc = (const float4*)(&g_WT[s][kc][0]);
                #pragma unroll
                for (int j = 0; j < (KT * G4 / 4) / NT; ++j)
                    ((float4*)wt)[tid + j * NT] = wsrc[tid + j * NT];
                __syncthreads();

                #pragma unroll 2
                for (int kk4 = 0; kk4 < KT; kk4 += 4) {
                    float4 a4[8];
                    #pragma unroll
                    for (int r = 0; r < 8; ++r)
                        a4[r] = *(const float4*)(src + (row0 + r) * H + kc + kk4);
                    #pragma unroll
                    for (int u = 0; u < 4; ++u) {
                        unsigned long long b2[8];
                        #pragma unroll
                        for (int g = 0; g < 4; ++g) {
                            ulonglong2 bb = *(const ulonglong2*)(wt + (kk4 + u) * G4 + g * 128 + colq);
                            b2[g * 2]     = bb.x;
                            b2[g * 2 + 1] = bb.y;
                        }
                        #pragma unroll
                        for (int r = 0; r < 8; ++r) {
                            float av = (u == 0) ? a4[r].x : (u == 1) ? a4[r].y
                                     : (u == 2) ? a4[r].z : a4[r].w;
                            unsigned long long a2;
                            asm("mov.b64 %0, {%1, %1};" : "=l"(a2) : "f"(av));
                            #pragma unroll
                            for (int q = 0; q < 8; ++q)
                                asm("fma.rn.f32x2 %0, %1, %2, %0;"
                                    : "+l"(acc2[r][q]) : "l"(a2), "l"(b2[q]));
                        }
                    }
                }
            }
        }
        __syncthreads();   // sync C: all GEMM reads of sh_h/sh_x done before pointwise writes

        // ---- pointwise LSTM cell update ----
        #pragma unroll
        for (int r = 0; r < 8; ++r) {
            int m = row0 + r;
            float4 cold = *(const float4*)(sh_c + m * H + colq);
            float cn[4], hn[4];
            #pragma unroll
            for (int q = 0; q < 4; ++q) {
                // gate value for gate g at offset q: acc2[r][g*2 + q/2], lane q%2
                unsigned long long vi = acc2[r][0 + (q >> 1)];
                unsigned long long vf = acc2[r][2 + (q >> 1)];
                unsigned long long vg = acc2[r][4 + (q >> 1)];
                unsigned long long vo = acc2[r][6 + (q >> 1)];
                float gi = (q & 1) ? hi_f32(vi) : lo_f32(vi);
                float gf = (q & 1) ? hi_f32(vf) : lo_f32(vf);
                float gg = (q & 1) ? hi_f32(vg) : lo_f32(vg);
                float go = (q & 1) ? hi_f32(vo) : lo_f32(vo);
                float iv = sigmoidf_fast(gi);
                float fv = sigmoidf_fast(gf);
                float gv = tanhf(gg);
                float ov = sigmoidf_fast(go);
                float cprev = (q == 0) ? cold.x : (q == 1) ? cold.y
                            : (q == 2) ? cold.z : cold.w;
                float cnew = fv * cprev + iv * gv;
                cn[q] = cnew;
                hn[q] = ov * tanhf(cnew);
            }
            *(float4*)(sh_c + m * H + colq) = make_float4(cn[0], cn[1], cn[2], cn[3]);
            *(float4*)(sh_h + m * H + colq) = make_float4(hn[0], hn[1], hn[2], hn[3]);
        }
    }

    __syncthreads();
    // ---- write h_final for this node block ----
    #pragma unroll
    for (int j = tid; j < NPC * H / 4; j += NT) {
        ((float4*)(out + (size_t)n0 * H))[j] = ((const float4*)sh_h)[j];
    }
}

extern "C" void kernel_launch(void* const* d_in, const int* in_sizes, int n_in,
                              void* d_out, int out_size) {
    // metadata order: x, index, W_ih, W_hh, b_ih, b_hh, dim_size
    const float* x    = (const float*)d_in[0];
    const float* Wih  = (const float*)d_in[2];
    const float* Whh  = (const float*)d_in[3];
    const float* bih  = (const float*)d_in[4];
    const float* bhh  = (const float*)d_in[5];
    float* out = (float*)d_out;

    transpose_w_kernel<<<(G4 * H + 255) / 256, 256>>>(Wih, Whh);

    const int smem_bytes = (3 * NPC * H + KT * G4 + G4) * (int)sizeof(float);
    static bool attr_set = false;
    if (!attr_set) {
        cudaFuncSetAttribute(lstm_agg_kernel,
                             cudaFuncAttributeMaxDynamicSharedMemorySize, smem_bytes);
        attr_set = true;
    }
    lstm_agg_kernel<<<N_NODES / NPC, NT, smem_bytes>>>(x, bih, bhh, out);
}